// round 16
// baseline (speedup 1.0000x reference)
#include <cuda_runtime.h>
#include <cuda_fp16.h>
#include <cstdint>
#include <math.h>

// ---------------- problem constants ----------------
#define B_    4
#define NQ_   2048
#define NK_   2048
#define DM    512
#define NH    8
#define DH    64
#define MTOT  (B_*NQ_)          // 8192 rows

// ---------------- scratch ----------------
__device__ float g_q [B_*NQ_*DM];
__device__ float g_k [B_*NK_*DM];   // fp16 K [b,key][dim] (half occupied)
__device__ float g_v [B_*NK_*DM];   // fp16 Vt [b,h,dim][key] (half occupied)
__device__ float g_h0[B_*NQ_*DM];
__device__ float g_h1[B_*NQ_*DM];
__device__ float g_h2[B_*NQ_*DM];

// ---------------- fp16 mma helpers ----------------
__device__ __forceinline__ void mma_f16(float* c, const unsigned* a, const unsigned* b){
    asm volatile("mma.sync.aligned.m16n8k16.row.col.f32.f16.f16.f32 "
        "{%0,%1,%2,%3}, {%4,%5,%6,%7}, {%8,%9}, {%0,%1,%2,%3};\n"
        : "+f"(c[0]), "+f"(c[1]), "+f"(c[2]), "+f"(c[3])
        : "r"(a[0]), "r"(a[1]), "r"(a[2]), "r"(a[3]), "r"(b[0]), "r"(b[1]));
}
__device__ __forceinline__ unsigned h2(float a, float b){
    __half2 h = __floats2half2_rn(a, b);
    return *reinterpret_cast<unsigned*>(&h);
}
__device__ __forceinline__ unsigned exp2h2(unsigned x){
    unsigned r; asm("ex2.approx.f16x2 %0, %1;" : "=r"(r) : "r"(x)); return r;
}
__device__ __forceinline__ unsigned smem_u32(const void* p){
    unsigned a;
    asm("{ .reg .u64 t; cvta.to.shared.u64 t, %1; cvt.u32.u64 %0, t; }" : "=r"(a) : "l"(p));
    return a;
}
#define CP_ASYNC16(dst_u32, src_ptr) \
    asm volatile("cp.async.cg.shared.global [%0], [%1], 16;\n" \
        :: "r"(dst_u32), "l"(src_ptr))
#define CP_COMMIT()  asm volatile("cp.async.commit_group;\n" ::: "memory")
#define CP_WAIT1()   asm volatile("cp.async.wait_group 1;\n" ::: "memory")
#define CP_WAIT0()   asm volatile("cp.async.wait_group 0;\n" ::: "memory")

// =====================================================================
// fp16 GEMM, double-buffered pipelined (R13/R15 winner) + output modes:
// MODE 0: fp32 out = A@W + bias
// MODE 1: fp32 out = res + relu(A@W + bias)
// MODE 2: fp16 out = A@W + bias            ([row][col] half2)
// MODE 3: fp16 TRANSPOSED out = A@W + bias  (vt[b,h,dim][key], for V)
// =====================================================================
#define GA_STR 20
#define GB_STR 132
#define GSM_WORDS (2*128*GA_STR + 2*16*GB_STR)   // 9344 words

template<int MODE>
__global__ void __launch_bounds__(256, 2)
gemm_f16(const float* __restrict__ A, const float* __restrict__ W,
         const float* __restrict__ bias, const float* __restrict__ res,
         float* __restrict__ out)
{
    __shared__ unsigned gsm[GSM_WORDS];
    unsigned (*sA)[128*GA_STR] = (unsigned(*)[128*GA_STR])gsm;
    unsigned (*sB)[16*GB_STR]  = (unsigned(*)[16*GB_STR])(gsm + 2*128*GA_STR);

    const int tid  = threadIdx.x;
    const int warp = tid >> 5, lane = tid & 31;
    const int g = lane >> 2, t = lane & 3;
    const int wm = (warp >> 2) * 64;
    const int wn = (warp & 3) * 32;
    const int bm = blockIdx.x * 128;
    const int bn = blockIdx.y * 128;

    const int ar  = tid >> 3;
    const int asub= tid & 7;
    const int wkp = tid >> 5;
    const int wng = tid & 31;

    float acc[4][4][4];
    #pragma unroll
    for (int i=0;i<4;i++) for (int j=0;j<4;j++) for (int r=0;r<4;r++) acc[i][j][r]=0.f;

    #pragma unroll
    for (int i=0;i<4;i++){
        int r = ar + 32*i;
        float4 va = *(const float4*)(A + (size_t)(bm + r)*512 + asub*4);
        *(uint2*)&sA[0][r*GA_STR + asub*2] = make_uint2(h2(va.x,va.y), h2(va.z,va.w));
    }
    #pragma unroll
    for (int i=0;i<2;i++){
        int kp = wkp + 8*i;
        float4 f0 = *(const float4*)(W + (size_t)(2*kp    )*512 + bn + wng*4);
        float4 f1 = *(const float4*)(W + (size_t)(2*kp + 1)*512 + bn + wng*4);
        *(uint4*)&sB[0][kp*GB_STR + wng*4] =
            make_uint4(h2(f0.x,f1.x), h2(f0.y,f1.y), h2(f0.z,f1.z), h2(f0.w,f1.w));
    }
    __syncthreads();

    for (int ki = 0; ki < 16; ki++){
        const int cur = ki & 1;

        float4 va[4], w0v[2], w1v[2];
        if (ki < 15){
            int kt = (ki + 1) * 32;
            #pragma unroll
            for (int i=0;i<4;i++)
                va[i] = *(const float4*)(A + (size_t)(bm + ar + 32*i)*512 + kt + asub*4);
            #pragma unroll
            for (int i=0;i<2;i++){
                int kp = wkp + 8*i;
                w0v[i] = *(const float4*)(W + (size_t)(kt + 2*kp    )*512 + bn + wng*4);
                w1v[i] = *(const float4*)(W + (size_t)(kt + 2*kp + 1)*512 + bn + wng*4);
            }
        }

        #pragma unroll
        for (int kk2=0; kk2<2; kk2++){
            unsigned af[4][4], bf[4][2];
            #pragma unroll
            for (int mf=0; mf<4; mf++){
                int rb = wm + mf*16 + g;
                int cb = kk2*8 + t;
                af[mf][0] = sA[cur][ rb     *GA_STR + cb    ];
                af[mf][1] = sA[cur][(rb + 8)*GA_STR + cb    ];
                af[mf][2] = sA[cur][ rb     *GA_STR + cb + 4];
                af[mf][3] = sA[cur][(rb + 8)*GA_STR + cb + 4];
            }
            #pragma unroll
            for (int nf=0; nf<4; nf++){
                int cb = wn + nf*8 + g;
                bf[nf][0] = sB[cur][(kk2*8 + t    )*GB_STR + cb];
                bf[nf][1] = sB[cur][(kk2*8 + t + 4)*GB_STR + cb];
            }
            #pragma unroll
            for (int mf=0; mf<4; mf++)
                #pragma unroll
                for (int nf=0; nf<4; nf++)
                    mma_f16(acc[mf][nf], af[mf], bf[nf]);
        }

        if (ki < 15){
            const int nb = cur ^ 1;
            #pragma unroll
            for (int i=0;i<4;i++)
                *(uint2*)&sA[nb][(ar + 32*i)*GA_STR + asub*2] =
                    make_uint2(h2(va[i].x,va[i].y), h2(va[i].z,va[i].w));
            #pragma unroll
            for (int i=0;i<2;i++){
                int kp = wkp + 8*i;
                *(uint4*)&sB[nb][kp*GB_STR + wng*4] =
                    make_uint4(h2(w0v[i].x,w1v[i].x), h2(w0v[i].y,w1v[i].y),
                               h2(w0v[i].z,w1v[i].z), h2(w0v[i].w,w1v[i].w));
            }
        }
        __syncthreads();
    }

    if (MODE == 3){
        __half* st = (__half*)gsm;           // 128 x 136 halves
        const int STR_T = 136;
        #pragma unroll
        for (int mf=0; mf<4; mf++){
            #pragma unroll
            for (int nf=0; nf<4; nf++){
                int row = wm + mf*16 + g;
                int col = wn + nf*8 + 2*t;
                float b0 = bias[bn + col], b1 = bias[bn + col + 1];
                st[(col  )*STR_T + row    ] = __float2half_rn(acc[mf][nf][0] + b0);
                st[(col+1)*STR_T + row    ] = __float2half_rn(acc[mf][nf][1] + b1);
                st[(col  )*STR_T + row + 8] = __float2half_rn(acc[mf][nf][2] + b0);
                st[(col+1)*STR_T + row + 8] = __float2half_rn(acc[mf][nf][3] + b1);
            }
        }
        __syncthreads();
        unsigned* vt = (unsigned*)out;
        const int dr = tid >> 1;
        const int hf = tid & 1;
        const int dg = bn + dr;
        const int hh = dg >> 6, dh = dg & 63;
        const int bb = bm >> 11, key0 = bm & 2047;
        unsigned* drow = vt + ((size_t)(bb*NH + hh)*DH + dh)*(NK_/2) + (key0 >> 1) + hf*32;
        const __half* srow = st + dr*STR_T + hf*64;
        #pragma unroll
        for (int i=0;i<8;i++)
            ((uint4*)drow)[i] = ((const uint4*)srow)[i];
        return;
    }

    #pragma unroll
    for (int mf=0; mf<4; mf++){
        #pragma unroll
        for (int nf=0; nf<4; nf++){
            int row = bm + wm + mf*16 + g;
            int col = bn + wn + nf*8 + 2*t;
            float b0 = bias[col], b1 = bias[col+1];
            float v0 = acc[mf][nf][0] + b0, v1 = acc[mf][nf][1] + b1;
            float v2 = acc[mf][nf][2] + b0, v3 = acc[mf][nf][3] + b1;
            if (MODE == 1){
                float2 r0 = *(const float2*)(res + (size_t)row*512 + col);
                float2 r1 = *(const float2*)(res + (size_t)(row+8)*512 + col);
                v0 = fmaxf(v0, 0.f) + r0.x;  v1 = fmaxf(v1, 0.f) + r0.y;
                v2 = fmaxf(v2, 0.f) + r1.x;  v3 = fmaxf(v3, 0.f) + r1.y;
            }
            if (MODE == 2){
                __half* o16 = (__half*)out;
                *(unsigned*)&o16[(size_t)row*512 + col]     = h2(v0, v1);
                *(unsigned*)&o16[(size_t)(row+8)*512 + col] = h2(v2, v3);
            } else {
                *(float2*)(out + (size_t)row*512 + col)      = make_float2(v0, v1);
                *(float2*)(out + (size_t)(row+8)*512 + col)  = make_float2(v2, v3);
            }
        }
    }
}

// =====================================================================
// Flash v11 = flash10 (cp.async double-buffered, BN=64) + flash6 softmax:
//   Q scaled by (1/sqrt(512))*log2(e) -> S in log2 domain
//   P = ex2.approx.f16x2(S)           -> 4 MUFU per kk (was 16 float expf)
//   l via ones-column MMA             -> fp32 accumulators, no scalar adds
// =====================================================================
#define QH2  36
#define KS10 36
#define VS10 36
#define FA11_SMEM ((128*QH2 + 2*64*KS10 + 2*64*VS10) * 4)   // 55296

__global__ void __launch_bounds__(128, 4)
flash11(const float* __restrict__ q, const unsigned* __restrict__ k16,
        const unsigned* __restrict__ vt, float* __restrict__ h0)
{
    extern __shared__ unsigned sm11[];
    unsigned* sQ  = sm11;
    unsigned* sK0 = sQ + 128*QH2;
    unsigned* sK1 = sK0 + 64*KS10;
    unsigned* sV0 = sK1 + 64*KS10;
    unsigned* sV1 = sV0 + 64*VS10;

    const int tid  = threadIdx.x;
    const int warp = tid >> 5, lane = tid & 31;
    const int g = lane >> 2, t = lane & 3;
    const int bh = blockIdx.y;
    const int b  = bh >> 3, h = bh & 7;
    const int m0 = blockIdx.x * 128;

    const size_t qbase  = (size_t)b*NQ_*DM + (size_t)h*DH;
    const size_t kbase2 = (size_t)b*NK_*(DM/2) + (size_t)h*(DH/2);
    const size_t vtbase = ((size_t)(b*NH + h)*DH)*(NK_/2);
    // (1/sqrt(512)) * log2(e): S in log2 domain -> p = 2^s
    const float sl = 0.044194173824159216f * 1.4426950408889634f;

    // ones-column B-frag (col 0 = 1.0) for the l-sum MMA
    const unsigned one_b = (g == 0) ? 0x3C003C00u : 0u;
    const unsigned bf1[2] = { one_b, one_b };

    const int seg = tid;
    const unsigned sK0a = smem_u32(sK0), sK1a = smem_u32(sK1);
    const unsigned sV0a = smem_u32(sV0), sV1a = smem_u32(sV1);

    // ---- stage Q tile once (sl folded in) ----
    #pragma unroll
    for (int it=0; it<8; it++){
        int idx = tid + 128*it;
        int row = idx >> 3, sub = idx & 7;
        const float* src = q + qbase + (size_t)(m0 + row)*DM + sub*8;
        float4 a4 = *(const float4*)(src);
        float4 b4 = *(const float4*)(src + 4);
        uint4 w = make_uint4(h2(sl*a4.x, sl*a4.y), h2(sl*a4.z, sl*a4.w),
                             h2(sl*b4.x, sl*b4.y), h2(sl*b4.z, sl*b4.w));
        *(uint4*)&sQ[row*QH2 + sub*4] = w;
    }

    float o[2][8][4];
    #pragma unroll
    for (int i=0;i<2;i++) for (int j=0;j<8;j++) for (int r=0;r<4;r++) o[i][j][r]=0.f;
    float lacc0[4] = {0.f,0.f,0.f,0.f};
    float lacc1[4] = {0.f,0.f,0.f,0.f};
    const int qr0 = warp*32 + g;

    // ---- prologue: async-stage tile 0 into buf0 ----
    #pragma unroll
    for (int it=0; it<4; it++){
        int s = seg + 128*it;
        int key = s >> 3, s8 = s & 7;
        CP_ASYNC16(sK0a + (key*KS10 + s8*4)*4,
                   k16 + kbase2 + (size_t)key*(DM/2) + s8*4);
        CP_ASYNC16(sV0a + (key*VS10 + s8*4)*4,
                   vt + vtbase + (size_t)key*(NK_/2) + s8*4);
    }
    CP_COMMIT();

    for (int itr = 0; itr < 32; itr++){
        const int cur = itr & 1;
        unsigned* sK = cur ? sK1 : sK0;
        unsigned* sV = cur ? sV1 : sV0;

        if (itr < 31){
            int kt = (itr + 1) * 64;
            unsigned ka = cur ? sK0a : sK1a;
            unsigned va = cur ? sV0a : sV1a;
            #pragma unroll
            for (int it=0; it<4; it++){
                int s = seg + 128*it;
                int key = s >> 3, s8 = s & 7;
                CP_ASYNC16(ka + (key*KS10 + s8*4)*4,
                           k16 + kbase2 + (size_t)(kt + key)*(DM/2) + s8*4);
                CP_ASYNC16(va + (key*VS10 + s8*4)*4,
                           vt + vtbase + (size_t)key*(NK_/2) + (kt>>1) + s8*4);
            }
            CP_COMMIT();
            CP_WAIT1();
        } else {
            CP_WAIT0();
        }
        __syncthreads();

        // ---- 4 groups of 16 keys ----
        #pragma unroll
        for (int kk=0; kk<4; kk++){
            float sa0[4]={0,0,0,0}, sb0[4]={0,0,0,0};
            float sa1[4]={0,0,0,0}, sb1[4]={0,0,0,0};
            #pragma unroll
            for (int ks=0; ks<4; ks++){
                unsigned qa[4], qb[4];
                int qa_ = qr0*QH2 + ks*8 + t;
                qa[0] = sQ[qa_];            qa[1] = sQ[qa_ + 8*QH2];
                qa[2] = sQ[qa_ + 4];        qa[3] = sQ[qa_ + 8*QH2 + 4];
                int qb_ = qa_ + 16*QH2;
                qb[0] = sQ[qb_];            qb[1] = sQ[qb_ + 8*QH2];
                qb[2] = sQ[qb_ + 4];        qb[3] = sQ[qb_ + 8*QH2 + 4];

                unsigned bfa[2], bfb[2];
                int ra_ = (kk*16 + g)*KS10 + ks*8 + t;
                int rb_ = ra_ + 8*KS10;
                bfa[0] = sK[ra_];  bfa[1] = sK[ra_ + 4];
                bfb[0] = sK[rb_];  bfb[1] = sK[rb_ + 4];
                mma_f16(sa0, qa, bfa);
                mma_f16(sb0, qa, bfb);
                mma_f16(sa1, qb, bfa);
                mma_f16(sb1, qb, bfb);
            }
            // P = 2^S elementwise in half2 (S already log2-domain)
            unsigned af0[4] = { exp2h2(h2(sa0[0],sa0[1])), exp2h2(h2(sa0[2],sa0[3])),
                                exp2h2(h2(sb0[0],sb0[1])), exp2h2(h2(sb0[2],sb0[3])) };
            unsigned af1[4] = { exp2h2(h2(sa1[0],sa1[1])), exp2h2(h2(sa1[2],sa1[3])),
                                exp2h2(h2(sb1[0],sb1[1])), exp2h2(h2(sb1[2],sb1[3])) };
            mma_f16(lacc0, af0, bf1);
            mma_f16(lacc1, af1, bf1);

            #pragma unroll
            for (int nf=0; nf<8; nf++){
                unsigned bf[2];
                int rv = (nf*8 + g)*VS10 + kk*8 + t;
                bf[0] = sV[rv];
                bf[1] = sV[rv + 4];
                mma_f16(o[0][nf], af0, bf);
                mma_f16(o[1][nf], af1, bf);
            }
        }
        __syncthreads();
    }

    // ---- l from col-0 accumulators (t==0 lane of each quad) ----
    const int src = lane & 28;
    float l0 = __shfl_sync(0xffffffffu, lacc0[0], src);
    float l1 = __shfl_sync(0xffffffffu, lacc0[2], src);
    float l2 = __shfl_sync(0xffffffffu, lacc1[0], src);
    float l3 = __shfl_sync(0xffffffffu, lacc1[2], src);
    float inv[4] = {1.f/l0, 1.f/l1, 1.f/l2, 1.f/l3};

    const int r0 = m0 + warp*32 + g;
    #pragma unroll
    for (int mf=0; mf<2; mf++){
        int rowa = r0 + mf*16;
        float ia = inv[mf*2], ib = inv[mf*2+1];
        size_t oa = qbase + (size_t)rowa*DM;
        #pragma unroll
        for (int nf=0; nf<8; nf++){
            int c = nf*8 + 2*t;
            float2 q0 = *(const float2*)(q + oa + c);
            float2 q1 = *(const float2*)(q + oa + (size_t)8*DM + c);
            *(float2*)(h0 + oa + c) =
                make_float2(o[mf][nf][0]*ia + q0.x, o[mf][nf][1]*ia + q0.y);
            *(float2*)(h0 + oa + (size_t)8*DM + c) =
                make_float2(o[mf][nf][2]*ib + q1.x, o[mf][nf][3]*ib + q1.y);
        }
    }
}

// =====================================================================
// LayerNorm (unchanged)
// =====================================================================
__global__ void __launch_bounds__(256)
ln_kernel(const float* __restrict__ x, const float* __restrict__ gam,
          const float* __restrict__ bet, float* __restrict__ y)
{
    const int row  = blockIdx.x*8 + (threadIdx.x >> 5);
    const int lane = threadIdx.x & 31;
    const float* xr = x + (size_t)row*DM;

    float4 vv[4];
    float s = 0.f, sq = 0.f;
    #pragma unroll
    for (int i=0;i<4;i++){
        vv[i] = *(const float4*)(xr + (lane + 32*i)*4);
        s  += vv[i].x + vv[i].y + vv[i].z + vv[i].w;
        sq += vv[i].x*vv[i].x + vv[i].y*vv[i].y + vv[i].z*vv[i].z + vv[i].w*vv[i].w;
    }
    #pragma unroll
    for (int off=16; off; off>>=1){
        s  += __shfl_xor_sync(0xffffffffu, s,  off);
        sq += __shfl_xor_sync(0xffffffffu, sq, off);
    }
    float mu  = s * (1.f/512.f);
    float var = sq * (1.f/512.f) - mu*mu;
    float rs  = rsqrtf(var + 1e-5f);

    float* yr = y + (size_t)row*DM;
    #pragma unroll
    for (int i=0;i<4;i++){
        int c = (lane + 32*i)*4;
        float4 gv = *(const float4*)(gam + c);
        float4 bv = *(const float4*)(bet + c);
        float4 ov;
        ov.x = (vv[i].x - mu)*rs*gv.x + bv.x;
        ov.y = (vv[i].y - mu)*rs*gv.y + bv.y;
        ov.z = (vv[i].z - mu)*rs*gv.z + bv.z;
        ov.w = (vv[i].w - mu)*rs*gv.w + bv.w;
        *(float4*)(yr + c) = ov;
    }
}

// =====================================================================
// kernel_launch
// =====================================================================
extern "C" void kernel_launch(void* const* d_in, const int* in_sizes, int n_in,
                              void* d_out, int out_size)
{
    (void)in_sizes; (void)n_in; (void)out_size;
    const float* Q    = (const float*)d_in[0];
    const float* K    = (const float*)d_in[1];
    const float* Wq   = (const float*)d_in[2];
    const float* bq   = (const float*)d_in[3];
    const float* Wk   = (const float*)d_in[4];
    const float* bk   = (const float*)d_in[5];
    const float* Wv   = (const float*)d_in[6];
    const float* bv   = (const float*)d_in[7];
    const float* Wo   = (const float*)d_in[8];
    const float* bo   = (const float*)d_in[9];
    const float* ln0g = (const float*)d_in[10];
    const float* ln0b = (const float*)d_in[11];
    const float* ln1g = (const float*)d_in[12];
    const float* ln1b = (const float*)d_in[13];
    float* out = (float*)d_out;

    float *qb, *kb, *vb, *h0, *h1, *h2;
    cudaGetSymbolAddress((void**)&qb, g_q);
    cudaGetSymbolAddress((void**)&kb, g_k);
    cudaGetSymbolAddress((void**)&vb, g_v);
    cudaGetSymbolAddress((void**)&h0, g_h0);
    cudaGetSymbolAddress((void**)&h1, g_h1);
    cudaGetSymbolAddress((void**)&h2, g_h2);

    cudaFuncSetAttribute(flash11,
        cudaFuncAttributeMaxDynamicSharedMemorySize, FA11_SMEM);

    dim3 ggrid(MTOT/128, 512/128);
    gemm_f16<0><<<ggrid, 256>>>(Q, Wq, bq, nullptr, qb);
    gemm_f16<2><<<ggrid, 256>>>(K, Wk, bk, nullptr, kb);   // fp16 K [key][dim]
    gemm_f16<3><<<ggrid, 256>>>(K, Wv, bv, nullptr, vb);   // fp16 Vt [b,h,dim][key]

    flash11<<<dim3(NQ_/128, B_*NH), 128, FA11_SMEM>>>(
        qb, (const unsigned*)kb, (const unsigned*)vb, h0);

    ln_kernel<<<MTOT/8, 256>>>(h0, ln0g, ln0b, h1);
    gemm_f16<1><<<ggrid, 256>>>(h1, Wo, bo, h1, h2);
    ln_kernel<<<MTOT/8, 256>>>(h2, ln1g, ln1b, out);
}

// round 17
// speedup vs baseline: 1.1325x; 1.1325x over previous
#include <cuda_runtime.h>
#include <cuda_fp16.h>
#include <cstdint>
#include <math.h>

// ---------------- problem constants ----------------
#define B_    4
#define NQ_   2048
#define NK_   2048
#define DM    512
#define NH    8
#define DH    64
#define MTOT  (B_*NQ_)          // 8192 rows

// ---------------- scratch ----------------
__device__ float g_q [B_*NQ_*DM];
__device__ float g_k [B_*NK_*DM];   // fp16 K [b,key][dim] (half occupied)
__device__ float g_v [B_*NK_*DM];   // fp16 Vt [b,h,dim][key] (half occupied)
__device__ float g_h0[B_*NQ_*DM];
__device__ float g_h1[B_*NQ_*DM];
__device__ float g_h2[B_*NQ_*DM];

// ---------------- fp16 mma helpers ----------------
__device__ __forceinline__ void mma_f16(float* c, const unsigned* a, const unsigned* b){
    asm volatile("mma.sync.aligned.m16n8k16.row.col.f32.f16.f16.f32 "
        "{%0,%1,%2,%3}, {%4,%5,%6,%7}, {%8,%9}, {%0,%1,%2,%3};\n"
        : "+f"(c[0]), "+f"(c[1]), "+f"(c[2]), "+f"(c[3])
        : "r"(a[0]), "r"(a[1]), "r"(a[2]), "r"(a[3]), "r"(b[0]), "r"(b[1]));
}
__device__ __forceinline__ unsigned h2(float a, float b){
    __half2 h = __floats2half2_rn(a, b);
    return *reinterpret_cast<unsigned*>(&h);
}
__device__ __forceinline__ float ex2f(float x){
    float r; asm("ex2.approx.f32 %0, %1;" : "=f"(r) : "f"(x)); return r;
}
__device__ __forceinline__ unsigned smem_u32(const void* p){
    unsigned a;
    asm("{ .reg .u64 t; cvta.to.shared.u64 t, %1; cvt.u32.u64 %0, t; }" : "=r"(a) : "l"(p));
    return a;
}
#define CP_ASYNC16(dst_u32, src_ptr) \
    asm volatile("cp.async.cg.shared.global [%0], [%1], 16;\n" \
        :: "r"(dst_u32), "l"(src_ptr))
#define CP_COMMIT()  asm volatile("cp.async.commit_group;\n" ::: "memory")
#define CP_WAIT1()   asm volatile("cp.async.wait_group 1;\n" ::: "memory")
#define CP_WAIT0()   asm volatile("cp.async.wait_group 0;\n" ::: "memory")

#define GA_STR 20
#define GB_STR 132
#define GSM_WORDS (2*128*GA_STR + 2*16*GB_STR)   // 9344 words

// =====================================================================
// Merged Q/K/V projection GEMM — ONE launch, grid (64, 4, 3):
//   z=0: fp32 q = Q@Wq + bq           (MODE 0)
//   z=1: fp16 k = K@Wk + bk           (MODE 2, [key][dim])
//   z=2: fp16 vt = (K@Wv + bv)^T      (MODE 3, [b,h,dim][key])
// Mainloop identical to the proven pipelined gemm; epilogue branches.
// =====================================================================
__global__ void __launch_bounds__(256, 2)
gemm_qkv(const float* __restrict__ Qin, const float* __restrict__ Kin,
         const float* __restrict__ Wq, const float* __restrict__ bq,
         const float* __restrict__ Wk, const float* __restrict__ bk,
         const float* __restrict__ Wv, const float* __restrict__ bv,
         float* __restrict__ qout, float* __restrict__ kout,
         float* __restrict__ vout)
{
    __shared__ unsigned gsm[GSM_WORDS];
    unsigned (*sA)[128*GA_STR] = (unsigned(*)[128*GA_STR])gsm;
    unsigned (*sB)[16*GB_STR]  = (unsigned(*)[16*GB_STR])(gsm + 2*128*GA_STR);

    const int z = blockIdx.z;
    const float* A    = (z == 0) ? Qin : Kin;
    const float* W    = (z == 0) ? Wq : (z == 1 ? Wk : Wv);
    const float* bias = (z == 0) ? bq : (z == 1 ? bk : bv);

    const int tid  = threadIdx.x;
    const int warp = tid >> 5, lane = tid & 31;
    const int g = lane >> 2, t = lane & 3;
    const int wm = (warp >> 2) * 64;
    const int wn = (warp & 3) * 32;
    const int bm = blockIdx.x * 128;
    const int bn = blockIdx.y * 128;

    const int ar  = tid >> 3;
    const int asub= tid & 7;
    const int wkp = tid >> 5;
    const int wng = tid & 31;

    float acc[4][4][4];
    #pragma unroll
    for (int i=0;i<4;i++) for (int j=0;j<4;j++) for (int r=0;r<4;r++) acc[i][j][r]=0.f;

    #pragma unroll
    for (int i=0;i<4;i++){
        int r = ar + 32*i;
        float4 va = *(const float4*)(A + (size_t)(bm + r)*512 + asub*4);
        *(uint2*)&sA[0][r*GA_STR + asub*2] = make_uint2(h2(va.x,va.y), h2(va.z,va.w));
    }
    #pragma unroll
    for (int i=0;i<2;i++){
        int kp = wkp + 8*i;
        float4 f0 = *(const float4*)(W + (size_t)(2*kp    )*512 + bn + wng*4);
        float4 f1 = *(const float4*)(W + (size_t)(2*kp + 1)*512 + bn + wng*4);
        *(uint4*)&sB[0][kp*GB_STR + wng*4] =
            make_uint4(h2(f0.x,f1.x), h2(f0.y,f1.y), h2(f0.z,f1.z), h2(f0.w,f1.w));
    }
    __syncthreads();

    for (int ki = 0; ki < 16; ki++){
        const int cur = ki & 1;

        float4 va[4], w0v[2], w1v[2];
        if (ki < 15){
            int kt = (ki + 1) * 32;
            #pragma unroll
            for (int i=0;i<4;i++)
                va[i] = *(const float4*)(A + (size_t)(bm + ar + 32*i)*512 + kt + asub*4);
            #pragma unroll
            for (int i=0;i<2;i++){
                int kp = wkp + 8*i;
                w0v[i] = *(const float4*)(W + (size_t)(kt + 2*kp    )*512 + bn + wng*4);
                w1v[i] = *(const float4*)(W + (size_t)(kt + 2*kp + 1)*512 + bn + wng*4);
            }
        }

        #pragma unroll
        for (int kk2=0; kk2<2; kk2++){
            unsigned af[4][4], bf[4][2];
            #pragma unroll
            for (int mf=0; mf<4; mf++){
                int rb = wm + mf*16 + g;
                int cb = kk2*8 + t;
                af[mf][0] = sA[cur][ rb     *GA_STR + cb    ];
                af[mf][1] = sA[cur][(rb + 8)*GA_STR + cb    ];
                af[mf][2] = sA[cur][ rb     *GA_STR + cb + 4];
                af[mf][3] = sA[cur][(rb + 8)*GA_STR + cb + 4];
            }
            #pragma unroll
            for (int nf=0; nf<4; nf++){
                int cb = wn + nf*8 + g;
                bf[nf][0] = sB[cur][(kk2*8 + t    )*GB_STR + cb];
                bf[nf][1] = sB[cur][(kk2*8 + t + 4)*GB_STR + cb];
            }
            #pragma unroll
            for (int mf=0; mf<4; mf++)
                #pragma unroll
                for (int nf=0; nf<4; nf++)
                    mma_f16(acc[mf][nf], af[mf], bf[nf]);
        }

        if (ki < 15){
            const int nb = cur ^ 1;
            #pragma unroll
            for (int i=0;i<4;i++)
                *(uint2*)&sA[nb][(ar + 32*i)*GA_STR + asub*2] =
                    make_uint2(h2(va[i].x,va[i].y), h2(va[i].z,va[i].w));
            #pragma unroll
            for (int i=0;i<2;i++){
                int kp = wkp + 8*i;
                *(uint4*)&sB[nb][kp*GB_STR + wng*4] =
                    make_uint4(h2(w0v[i].x,w1v[i].x), h2(w0v[i].y,w1v[i].y),
                               h2(w0v[i].z,w1v[i].z), h2(w0v[i].w,w1v[i].w));
            }
        }
        __syncthreads();
    }

    if (z == 2){
        // transposed fp16 epilogue -> vt[b,h,dim][key]
        __half* st = (__half*)gsm;
        const int STR_T = 136;
        #pragma unroll
        for (int mf=0; mf<4; mf++){
            #pragma unroll
            for (int nf=0; nf<4; nf++){
                int row = wm + mf*16 + g;
                int col = wn + nf*8 + 2*t;
                float b0 = bias[bn + col], b1 = bias[bn + col + 1];
                st[(col  )*STR_T + row    ] = __float2half_rn(acc[mf][nf][0] + b0);
                st[(col+1)*STR_T + row    ] = __float2half_rn(acc[mf][nf][1] + b1);
                st[(col  )*STR_T + row + 8] = __float2half_rn(acc[mf][nf][2] + b0);
                st[(col+1)*STR_T + row + 8] = __float2half_rn(acc[mf][nf][3] + b1);
            }
        }
        __syncthreads();
        unsigned* vtp = (unsigned*)vout;
        const int dr = tid >> 1;
        const int hf = tid & 1;
        const int dg = bn + dr;
        const int hh = dg >> 6, dh = dg & 63;
        const int bb = bm >> 11, key0 = bm & 2047;
        unsigned* drow = vtp + ((size_t)(bb*NH + hh)*DH + dh)*(NK_/2) + (key0 >> 1) + hf*32;
        const __half* srow = st + dr*STR_T + hf*64;
        #pragma unroll
        for (int i=0;i<8;i++)
            ((uint4*)drow)[i] = ((const uint4*)srow)[i];
        return;
    }

    #pragma unroll
    for (int mf=0; mf<4; mf++){
        #pragma unroll
        for (int nf=0; nf<4; nf++){
            int row = bm + wm + mf*16 + g;
            int col = bn + wn + nf*8 + 2*t;
            float b0 = bias[col], b1 = bias[col+1];
            float v0 = acc[mf][nf][0] + b0, v1 = acc[mf][nf][1] + b1;
            float v2 = acc[mf][nf][2] + b0, v3 = acc[mf][nf][3] + b1;
            if (z == 1){
                __half* o16 = (__half*)kout;
                *(unsigned*)&o16[(size_t)row*512 + col]     = h2(v0, v1);
                *(unsigned*)&o16[(size_t)(row+8)*512 + col] = h2(v2, v3);
            } else {
                *(float2*)(qout + (size_t)row*512 + col)      = make_float2(v0, v1);
                *(float2*)(qout + (size_t)(row+8)*512 + col)  = make_float2(v2, v3);
            }
        }
    }
}

// =====================================================================
// FFN GEMM (proven R13/R15): fp32 out = res + relu(A@W + bias)
// =====================================================================
__global__ void __launch_bounds__(256, 2)
gemm_ffn(const float* __restrict__ A, const float* __restrict__ W,
         const float* __restrict__ bias, const float* __restrict__ res,
         float* __restrict__ out)
{
    __shared__ unsigned gsm[GSM_WORDS];
    unsigned (*sA)[128*GA_STR] = (unsigned(*)[128*GA_STR])gsm;
    unsigned (*sB)[16*GB_STR]  = (unsigned(*)[16*GB_STR])(gsm + 2*128*GA_STR);

    const int tid  = threadIdx.x;
    const int warp = tid >> 5, lane = tid & 31;
    const int g = lane >> 2, t = lane & 3;
    const int wm = (warp >> 2) * 64;
    const int wn = (warp & 3) * 32;
    const int bm = blockIdx.x * 128;
    const int bn = blockIdx.y * 128;

    const int ar  = tid >> 3;
    const int asub= tid & 7;
    const int wkp = tid >> 5;
    const int wng = tid & 31;

    float acc[4][4][4];
    #pragma unroll
    for (int i=0;i<4;i++) for (int j=0;j<4;j++) for (int r=0;r<4;r++) acc[i][j][r]=0.f;

    #pragma unroll
    for (int i=0;i<4;i++){
        int r = ar + 32*i;
        float4 va = *(const float4*)(A + (size_t)(bm + r)*512 + asub*4);
        *(uint2*)&sA[0][r*GA_STR + asub*2] = make_uint2(h2(va.x,va.y), h2(va.z,va.w));
    }
    #pragma unroll
    for (int i=0;i<2;i++){
        int kp = wkp + 8*i;
        float4 f0 = *(const float4*)(W + (size_t)(2*kp    )*512 + bn + wng*4);
        float4 f1 = *(const float4*)(W + (size_t)(2*kp + 1)*512 + bn + wng*4);
        *(uint4*)&sB[0][kp*GB_STR + wng*4] =
            make_uint4(h2(f0.x,f1.x), h2(f0.y,f1.y), h2(f0.z,f1.z), h2(f0.w,f1.w));
    }
    __syncthreads();

    for (int ki = 0; ki < 16; ki++){
        const int cur = ki & 1;

        float4 va[4], w0v[2], w1v[2];
        if (ki < 15){
            int kt = (ki + 1) * 32;
            #pragma unroll
            for (int i=0;i<4;i++)
                va[i] = *(const float4*)(A + (size_t)(bm + ar + 32*i)*512 + kt + asub*4);
            #pragma unroll
            for (int i=0;i<2;i++){
                int kp = wkp + 8*i;
                w0v[i] = *(const float4*)(W + (size_t)(kt + 2*kp    )*512 + bn + wng*4);
                w1v[i] = *(const float4*)(W + (size_t)(kt + 2*kp + 1)*512 + bn + wng*4);
            }
        }

        #pragma unroll
        for (int kk2=0; kk2<2; kk2++){
            unsigned af[4][4], bf[4][2];
            #pragma unroll
            for (int mf=0; mf<4; mf++){
                int rb = wm + mf*16 + g;
                int cb = kk2*8 + t;
                af[mf][0] = sA[cur][ rb     *GA_STR + cb    ];
                af[mf][1] = sA[cur][(rb + 8)*GA_STR + cb    ];
                af[mf][2] = sA[cur][ rb     *GA_STR + cb + 4];
                af[mf][3] = sA[cur][(rb + 8)*GA_STR + cb + 4];
            }
            #pragma unroll
            for (int nf=0; nf<4; nf++){
                int cb = wn + nf*8 + g;
                bf[nf][0] = sB[cur][(kk2*8 + t    )*GB_STR + cb];
                bf[nf][1] = sB[cur][(kk2*8 + t + 4)*GB_STR + cb];
            }
            #pragma unroll
            for (int mf=0; mf<4; mf++)
                #pragma unroll
                for (int nf=0; nf<4; nf++)
                    mma_f16(acc[mf][nf], af[mf], bf[nf]);
        }

        if (ki < 15){
            const int nb = cur ^ 1;
            #pragma unroll
            for (int i=0;i<4;i++)
                *(uint2*)&sA[nb][(ar + 32*i)*GA_STR + asub*2] =
                    make_uint2(h2(va[i].x,va[i].y), h2(va[i].z,va[i].w));
            #pragma unroll
            for (int i=0;i<2;i++){
                int kp = wkp + 8*i;
                *(uint4*)&sB[nb][kp*GB_STR + wng*4] =
                    make_uint4(h2(w0v[i].x,w1v[i].x), h2(w0v[i].y,w1v[i].y),
                               h2(w0v[i].z,w1v[i].z), h2(w0v[i].w,w1v[i].w));
            }
        }
        __syncthreads();
    }

    #pragma unroll
    for (int mf=0; mf<4; mf++){
        #pragma unroll
        for (int nf=0; nf<4; nf++){
            int row = bm + wm + mf*16 + g;
            int col = bn + wn + nf*8 + 2*t;
            float b0 = bias[col], b1 = bias[col+1];
            float v0 = acc[mf][nf][0] + b0, v1 = acc[mf][nf][1] + b1;
            float v2 = acc[mf][nf][2] + b0, v3 = acc[mf][nf][3] + b1;
            float2 r0 = *(const float2*)(res + (size_t)row*512 + col);
            float2 r1 = *(const float2*)(res + (size_t)(row+8)*512 + col);
            v0 = fmaxf(v0, 0.f) + r0.x;  v1 = fmaxf(v1, 0.f) + r0.y;
            v2 = fmaxf(v2, 0.f) + r1.x;  v3 = fmaxf(v3, 0.f) + r1.y;
            *(float2*)(out + (size_t)row*512 + col)      = make_float2(v0, v1);
            *(float2*)(out + (size_t)(row+8)*512 + col)  = make_float2(v2, v3);
        }
    }
}

// =====================================================================
// Flash v12 = flash10 (R15 winner) with log2-domain Q + raw ex2.approx.f32
// (scalar la adds kept — NO l-MMA). Everything else byte-identical.
// =====================================================================
#define QH2  36
#define KS10 36
#define VS10 36
#define FA12_SMEM ((128*QH2 + 2*64*KS10 + 2*64*VS10) * 4)   // 55296

__global__ void __launch_bounds__(128, 4)
flash12(const float* __restrict__ q, const unsigned* __restrict__ k16,
        const unsigned* __restrict__ vt, float* __restrict__ h0)
{
    extern __shared__ unsigned sm12[];
    unsigned* sQ  = sm12;
    unsigned* sK0 = sQ + 128*QH2;
    unsigned* sK1 = sK0 + 64*KS10;
    unsigned* sV0 = sK1 + 64*KS10;
    unsigned* sV1 = sV0 + 64*VS10;

    const int tid  = threadIdx.x;
    const int warp = tid >> 5, lane = tid & 31;
    const int g = lane >> 2, t = lane & 3;
    const int bh = blockIdx.y;
    const int b  = bh >> 3, h = bh & 7;
    const int m0 = blockIdx.x * 128;

    const size_t qbase  = (size_t)b*NQ_*DM + (size_t)h*DH;
    const size_t kbase2 = (size_t)b*NK_*(DM/2) + (size_t)h*(DH/2);
    const size_t vtbase = ((size_t)(b*NH + h)*DH)*(NK_/2);
    // (1/sqrt(512)) * log2(e): S in log2 domain -> p = 2^s (ex2)
    const float sl = 0.044194173824159216f * 1.4426950408889634f;

    const int seg = tid;
    const unsigned sK0a = smem_u32(sK0), sK1a = smem_u32(sK1);
    const unsigned sV0a = smem_u32(sV0), sV1a = smem_u32(sV1);

    // ---- stage Q tile once (sl folded in) ----
    #pragma unroll
    for (int it=0; it<8; it++){
        int idx = tid + 128*it;
        int row = idx >> 3, sub = idx & 7;
        const float* src = q + qbase + (size_t)(m0 + row)*DM + sub*8;
        float4 a4 = *(const float4*)(src);
        float4 b4 = *(const float4*)(src + 4);
        uint4 w = make_uint4(h2(sl*a4.x, sl*a4.y), h2(sl*a4.z, sl*a4.w),
                             h2(sl*b4.x, sl*b4.y), h2(sl*b4.z, sl*b4.w));
        *(uint4*)&sQ[row*QH2 + sub*4] = w;
    }

    float o[2][8][4];
    #pragma unroll
    for (int i=0;i<2;i++) for (int j=0;j<8;j++) for (int r=0;r<4;r++) o[i][j][r]=0.f;
    float la[4] = {0.f, 0.f, 0.f, 0.f};
    const int qr0 = warp*32 + g;

    // ---- prologue: async-stage tile 0 into buf0 ----
    #pragma unroll
    for (int it=0; it<4; it++){
        int s = seg + 128*it;
        int key = s >> 3, s8 = s & 7;
        CP_ASYNC16(sK0a + (key*KS10 + s8*4)*4,
                   k16 + kbase2 + (size_t)key*(DM/2) + s8*4);
        CP_ASYNC16(sV0a + (key*VS10 + s8*4)*4,
                   vt + vtbase + (size_t)key*(NK_/2) + s8*4);
    }
    CP_COMMIT();

    for (int itr = 0; itr < 32; itr++){
        const int cur = itr & 1;
        unsigned* sK = cur ? sK1 : sK0;
        unsigned* sV = cur ? sV1 : sV0;

        if (itr < 31){
            int kt = (itr + 1) * 64;
            unsigned ka = cur ? sK0a : sK1a;
            unsigned va = cur ? sV0a : sV1a;
            #pragma unroll
            for (int it=0; it<4; it++){
                int s = seg + 128*it;
                int key = s >> 3, s8 = s & 7;
                CP_ASYNC16(ka + (key*KS10 + s8*4)*4,
                           k16 + kbase2 + (size_t)(kt + key)*(DM/2) + s8*4);
                CP_ASYNC16(va + (key*VS10 + s8*4)*4,
                           vt + vtbase + (size_t)key*(NK_/2) + (kt>>1) + s8*4);
            }
            CP_COMMIT();
            CP_WAIT1();
        } else {
            CP_WAIT0();
        }
        __syncthreads();

        #pragma unroll
        for (int kk=0; kk<4; kk++){
            float sa0[4]={0,0,0,0}, sb0[4]={0,0,0,0};
            float sa1[4]={0,0,0,0}, sb1[4]={0,0,0,0};
            #pragma unroll
            for (int ks=0; ks<4; ks++){
                unsigned qa[4], qb[4];
                int qa_ = qr0*QH2 + ks*8 + t;
                qa[0] = sQ[qa_];            qa[1] = sQ[qa_ + 8*QH2];
                qa[2] = sQ[qa_ + 4];        qa[3] = sQ[qa_ + 8*QH2 + 4];
                int qb_ = qa_ + 16*QH2;
                qb[0] = sQ[qb_];            qb[1] = sQ[qb_ + 8*QH2];
                qb[2] = sQ[qb_ + 4];        qb[3] = sQ[qb_ + 8*QH2 + 4];

                unsigned bfa[2], bfb[2];
                int ra_ = (kk*16 + g)*KS10 + ks*8 + t;
                int rb_ = ra_ + 8*KS10;
                bfa[0] = sK[ra_];  bfa[1] = sK[ra_ + 4];
                bfb[0] = sK[rb_];  bfb[1] = sK[rb_ + 4];
                mma_f16(sa0, qa, bfa);
                mma_f16(sb0, qa, bfb);
                mma_f16(sa1, qb, bfa);
                mma_f16(sb1, qb, bfb);
            }
            // p = 2^s (single MUFU each; S already log2-domain)
            float ea0 = ex2f(sa0[0]), ea1 = ex2f(sa0[1]);
            float ea2 = ex2f(sa0[2]), ea3 = ex2f(sa0[3]);
            float eb0 = ex2f(sb0[0]), eb1 = ex2f(sb0[1]);
            float eb2 = ex2f(sb0[2]), eb3 = ex2f(sb0[3]);
            float fa0 = ex2f(sa1[0]), fa1 = ex2f(sa1[1]);
            float fa2 = ex2f(sa1[2]), fa3 = ex2f(sa1[3]);
            float fb0 = ex2f(sb1[0]), fb1 = ex2f(sb1[1]);
            float fb2 = ex2f(sb1[2]), fb3 = ex2f(sb1[3]);
            la[0] += ea0 + ea1 + eb0 + eb1;
            la[1] += ea2 + ea3 + eb2 + eb3;
            la[2] += fa0 + fa1 + fb0 + fb1;
            la[3] += fa2 + fa3 + fb2 + fb3;
            unsigned af0[4] = { h2(ea0,ea1), h2(ea2,ea3), h2(eb0,eb1), h2(eb2,eb3) };
            unsigned af1[4] = { h2(fa0,fa1), h2(fa2,fa3), h2(fb0,fb1), h2(fb2,fb3) };

            #pragma unroll
            for (int nf=0; nf<8; nf++){
                unsigned bf[2];
                int rv = (nf*8 + g)*VS10 + kk*8 + t;
                bf[0] = sV[rv];
                bf[1] = sV[rv + 4];
                mma_f16(o[0][nf], af0, bf);
                mma_f16(o[1][nf], af1, bf);
            }
        }
        __syncthreads();
    }

    // ---- final l reduction + normalize + q residual ----
    #pragma unroll
    for (int i=0;i<4;i++){
        la[i] += __shfl_xor_sync(0xffffffffu, la[i], 1);
        la[i] += __shfl_xor_sync(0xffffffffu, la[i], 2);
    }
    float inv[4] = {1.f/la[0], 1.f/la[1], 1.f/la[2], 1.f/la[3]};

    const int r0 = m0 + warp*32 + g;
    #pragma unroll
    for (int mf=0; mf<2; mf++){
        int rowa = r0 + mf*16;
        float ia = inv[mf*2], ib = inv[mf*2+1];
        size_t oa = qbase + (size_t)rowa*DM;
        #pragma unroll
        for (int nf=0; nf<8; nf++){
            int c = nf*8 + 2*t;
            float2 q0 = *(const float2*)(q + oa + c);
            float2 q1 = *(const float2*)(q + oa + (size_t)8*DM + c);
            *(float2*)(h0 + oa + c) =
                make_float2(o[mf][nf][0]*ia + q0.x, o[mf][nf][1]*ia + q0.y);
            *(float2*)(h0 + oa + (size_t)8*DM + c) =
                make_float2(o[mf][nf][2]*ib + q1.x, o[mf][nf][3]*ib + q1.y);
        }
    }
}

// =====================================================================
// LayerNorm (unchanged)
// =====================================================================
__global__ void __launch_bounds__(256)
ln_kernel(const float* __restrict__ x, const float* __restrict__ gam,
          const float* __restrict__ bet, float* __restrict__ y)
{
    const int row  = blockIdx.x*8 + (threadIdx.x >> 5);
    const int lane = threadIdx.x & 31;
    const float* xr = x + (size_t)row*DM;

    float4 vv[4];
    float s = 0.f, sq = 0.f;
    #pragma unroll
    for (int i=0;i<4;i++){
        vv[i] = *(const float4*)(xr + (lane + 32*i)*4);
        s  += vv[i].x + vv[i].y + vv[i].z + vv[i].w;
        sq += vv[i].x*vv[i].x + vv[i].y*vv[i].y + vv[i].z*vv[i].z + vv[i].w*vv[i].w;
    }
    #pragma unroll
    for (int off=16; off; off>>=1){
        s  += __shfl_xor_sync(0xffffffffu, s,  off);
        sq += __shfl_xor_sync(0xffffffffu, sq, off);
    }
    float mu  = s * (1.f/512.f);
    float var = sq * (1.f/512.f) - mu*mu;
    float rs  = rsqrtf(var + 1e-5f);

    float* yr = y + (size_t)row*DM;
    #pragma unroll
    for (int i=0;i<4;i++){
        int c = (lane + 32*i)*4;
        float4 gv = *(const float4*)(gam + c);
        float4 bv = *(const float4*)(bet + c);
        float4 ov;
        ov.x = (vv[i].x - mu)*rs*gv.x + bv.x;
        ov.y = (vv[i].y - mu)*rs*gv.y + bv.y;
        ov.z = (vv[i].z - mu)*rs*gv.z + bv.z;
        ov.w = (vv[i].w - mu)*rs*gv.w + bv.w;
        *(float4*)(yr + c) = ov;
    }
}

// =====================================================================
// kernel_launch — 5 launches total
// =====================================================================
extern "C" void kernel_launch(void* const* d_in, const int* in_sizes, int n_in,
                              void* d_out, int out_size)
{
    (void)in_sizes; (void)n_in; (void)out_size;
    const float* Q    = (const float*)d_in[0];
    const float* K    = (const float*)d_in[1];
    const float* Wq   = (const float*)d_in[2];
    const float* bq   = (const float*)d_in[3];
    const float* Wk   = (const float*)d_in[4];
    const float* bk   = (const float*)d_in[5];
    const float* Wv   = (const float*)d_in[6];
    const float* bv   = (const float*)d_in[7];
    const float* Wo   = (const float*)d_in[8];
    const float* bo   = (const float*)d_in[9];
    const float* ln0g = (const float*)d_in[10];
    const float* ln0b = (const float*)d_in[11];
    const float* ln1g = (const float*)d_in[12];
    const float* ln1b = (const float*)d_in[13];
    float* out = (float*)d_out;

    float *qb, *kb, *vb, *h0, *h1, *h2;
    cudaGetSymbolAddress((void**)&qb, g_q);
    cudaGetSymbolAddress((void**)&kb, g_k);
    cudaGetSymbolAddress((void**)&vb, g_v);
    cudaGetSymbolAddress((void**)&h0, g_h0);
    cudaGetSymbolAddress((void**)&h1, g_h1);
    cudaGetSymbolAddress((void**)&h2, g_h2);

    cudaFuncSetAttribute(flash12,
        cudaFuncAttributeMaxDynamicSharedMemorySize, FA12_SMEM);

    // merged Q/K/V projections: one launch, grid (64,4,3)
    gemm_qkv<<<dim3(MTOT/128, 4, 3), 256>>>(Q, K, Wq, bq, Wk, bk, Wv, bv,
                                            qb, kb, vb);

    flash12<<<dim3(NQ_/128, B_*NH), 128, FA12_SMEM>>>(
        qb, (const unsigned*)kb, (const unsigned*)vb, h0);

    ln_kernel<<<MTOT/8, 256>>>(h0, ln0g, ln0b, h1);
    gemm_ffn<<<dim3(MTOT/128, 4), 256>>>(h1, Wo, bo, h1, h2);
    ln_kernel<<<MTOT/8, 256>>>(h2, ln1g, ln1b, out);
}